// round 17
// baseline (speedup 1.0000x reference)
#include <cuda_runtime.h>
#include <cuda_fp16.h>
#include <math.h>
#include <stdint.h>

// Problem dims (fixed by the reference)
#define BB   16384   // batch (img rows)
#define DD   512     // feature dim
#define NT   4096    // n text
#define HH   1024    // hidden

typedef __half hf;

// ---------------- scratch (device globals; no allocs allowed) ----------------
__device__ hf g_img_h [ (size_t)BB * DD ];
__device__ hf g_txtT_h[ (size_t)NT * DD ];
__device__ hf g_ht1_h [ (size_t)NT * HH ];
__device__ hf g_ht2_h [ (size_t)NT * HH ];
__device__ hf g_ptxt_h[ (size_t)NT * DD ];              // B of sim: single fp16
__device__ hf g_hi1_h [ (size_t)BB * HH ];
__device__ hf g_hi2_h [ (size_t)BB * HH ];
__device__ hf g_pimg_h[ (size_t)BB * DD ];              // A of sim: single fp16
__device__ hf g_Wi0T  [ (size_t)HH * DD ];
__device__ hf g_Wi1T  [ (size_t)HH * HH ];
__device__ hf g_Wi2T  [ (size_t)DD * HH ];
__device__ hf g_Wt0T  [ (size_t)HH * DD ];
__device__ hf g_Wt1T  [ (size_t)HH * HH ];
__device__ hf g_Wt2T  [ (size_t)DD * HH ];
__device__ hf g_sim  [ (size_t)BB * NT ];               // fp16 sim (128 MB)
__device__ float g_rowsq [ BB ];
__device__ unsigned long long g_rowmax[ BB ];
__device__ float g_picked [ BB ];
__device__ int   g_correct[ BB ];

__device__ __forceinline__ uint32_t mono_f(float v) {
    uint32_t u = __float_as_uint(v);
    return (u & 0x80000000u) ? ~u : (u | 0x80000000u);
}
__device__ __forceinline__ unsigned long long pack_mi(float v, int idx) {
    return ((unsigned long long)mono_f(v) << 32) | (uint32_t)(~(uint32_t)idx);
}

// ---------------- elementwise fp32 -> fp16 convert ----------------
__global__ __launch_bounds__(256)
void cvt_k(const float* __restrict__ in, hf* __restrict__ out, size_t n4) {
    size_t i = (size_t)blockIdx.x * 256 + threadIdx.x;
    size_t stride = (size_t)gridDim.x * 256;
    for (; i < n4; i += stride) {
        float4 v = reinterpret_cast<const float4*>(in)[i];
        hf h[4];
        h[0] = __float2half_rn(v.x); h[1] = __float2half_rn(v.y);
        h[2] = __float2half_rn(v.z); h[3] = __float2half_rn(v.w);
        reinterpret_cast<uint2*>(out)[i] = *reinterpret_cast<uint2*>(h);
    }
}

// ------ batched transpose: 7 tensors in ONE launch (fp16 single output) -----
struct TDesc { const float* in; hf* hi; int R; int C; };
struct TP7   { TDesc d[7]; };

__global__ void transpose_multi_k(TP7 p) {
    const TDesc d = p.d[blockIdx.z];
    const int c0 = blockIdx.x * 32, r0 = blockIdx.y * 32;
    if (c0 >= d.C || r0 >= d.R) return;
    __shared__ float t[32][33];
    const int c = c0 + threadIdx.x;
    #pragma unroll
    for (int i = 0; i < 32; i += 8) {
        int r = r0 + threadIdx.y + i;
        t[threadIdx.y + i][threadIdx.x] = d.in[(size_t)r * d.C + c];
    }
    __syncthreads();
    const int oc = r0 + threadIdx.x;
    #pragma unroll
    for (int i = 0; i < 32; i += 8) {
        int orow = c0 + threadIdx.y + i;
        d.hi[(size_t)orow * d.R + oc] = __float2half_rn(t[threadIdx.x][threadIdx.y + i]);
    }
}

// ====== mma.sync FP16 GEMM  C[M,N] = A[M,K] * B[N,K]^T =====================
// Block 128x128, BK=64, 8 warps (32m x 64n warp tile), 3-stage cp.async,
// single __syncthreads per K-iter, 2 CTAs per SM. Optional fused row stats.

#define LDH 72                        // halves per smem row (64 + 8 pad) = 144B
#define A_TERM_B (128 * LDH * 2)      // 18432 B
#define B_TERM_B (128 * LDH * 2)      // 18432 B
#define STAGE_B  (A_TERM_B + B_TERM_B)   // 36864 B
#define NSTAGE   3
#define GEMM_SMEM (NSTAGE * STAGE_B)  // 110592 B -> 2 CTAs/SM

__device__ __forceinline__ uint32_t smem_u32(const void* p) {
    uint32_t a;
    asm("{ .reg .u64 t; cvta.to.shared.u64 t, %1; cvt.u32.u64 %0, t; }" : "=r"(a) : "l"(p));
    return a;
}
__device__ __forceinline__ void cp16(uint32_t dst, const void* src) {
    asm volatile("cp.async.cg.shared.global [%0], [%1], 16;" :: "r"(dst), "l"(src));
}
__device__ __forceinline__ void ldm_x4(uint32_t& r0, uint32_t& r1, uint32_t& r2,
                                       uint32_t& r3, uint32_t addr) {
    asm volatile("ldmatrix.sync.aligned.m8n8.x4.shared.b16 {%0,%1,%2,%3}, [%4];"
                 : "=r"(r0), "=r"(r1), "=r"(r2), "=r"(r3) : "r"(addr));
}
__device__ __forceinline__ void mma16(float* c, const uint32_t* a, uint32_t b0, uint32_t b1) {
    asm volatile(
        "mma.sync.aligned.m16n8k16.row.col.f32.f16.f16.f32 "
        "{%0,%1,%2,%3}, {%4,%5,%6,%7}, {%8,%9}, {%0,%1,%2,%3};"
        : "+f"(c[0]), "+f"(c[1]), "+f"(c[2]), "+f"(c[3])
        : "r"(a[0]), "r"(a[1]), "r"(a[2]), "r"(a[3]), "r"(b0), "r"(b1));
}

__global__ __launch_bounds__(256, 2)
void gemm_mma(const hf* __restrict__ Ah,
              const hf* __restrict__ Bh,
              const float* __restrict__ bias,
              hf* __restrict__ Ch,
              float* __restrict__ rowsq,                 // fused stats (may be null)
              unsigned long long* __restrict__ rowmax,
              int M, int N, int K, int relu)
{
    extern __shared__ char smraw[];
    const uint32_t smb = smem_u32(smraw);

    const int tid  = threadIdx.x;
    const int lane = tid & 31;
    const int wid  = tid >> 5;
    const int wm   = wid & 3;
    const int wn   = wid >> 2;
    const int bm   = blockIdx.y * 128;
    const int bn   = blockIdx.x * 128;
    const int KI   = K >> 6;

    const int lr = tid >> 3;
    const int lc = tid & 7;

    auto load_stage = [&](int buf, int it) {
        const int k0 = it << 6;
        const uint32_t st = smb + (uint32_t)buf * STAGE_B;
        const uint32_t ah_s = st;
        const uint32_t bh_s = st + A_TERM_B;
        #pragma unroll
        for (int p = 0; p < 4; ++p) {
            const int row = lr + p * 32;
            const size_t g = (size_t)(bm + row) * K + k0 + lc * 8;
            const uint32_t s = (uint32_t)(row * (LDH * 2) + lc * 16);
            cp16(ah_s + s, Ah + g);
        }
        #pragma unroll
        for (int p = 0; p < 4; ++p) {
            const int row = lr + p * 32;
            const size_t g = (size_t)(bn + row) * K + k0 + lc * 8;
            const uint32_t s = (uint32_t)(row * (LDH * 2) + lc * 16);
            cp16(bh_s + s, Bh + g);
        }
        asm volatile("cp.async.commit_group;");
    };

    const uint32_t a_off = (uint32_t)((lane & 15) * (LDH * 2) + (lane >> 4) * 16);
    const uint32_t b_off = (uint32_t)(((lane & 7) + ((lane >> 4) << 3)) * (LDH * 2)
                                      + ((lane >> 3) & 1) * 16);

    float acc[2][8][4];
    #pragma unroll
    for (int i = 0; i < 2; ++i)
        #pragma unroll
        for (int j = 0; j < 8; ++j)
            #pragma unroll
            for (int q = 0; q < 4; ++q) acc[i][j][q] = 0.0f;

    // prologue: stages 0,1 in flight; wait for stage 0
    load_stage(0, 0);
    load_stage(1, 1);
    asm volatile("cp.async.wait_group 1;");
    __syncthreads();

    for (int it = 0; it < KI; ++it) {
        // issue stage it+2 into buffer (it+2)%3 first (freed by last iter's sync)
        const int nt = it + 2;
        if (nt < KI) load_stage(nt - (nt / NSTAGE) * NSTAGE, nt);
        else         asm volatile("cp.async.commit_group;");

        const int buf = it - (it / NSTAGE) * NSTAGE;
        const uint32_t st = smb + (uint32_t)buf * STAGE_B;
        const uint32_t a_h = st + (uint32_t)(wm * 32) * (LDH * 2) + a_off;
        const uint32_t b_h = st + A_TERM_B + (uint32_t)(wn * 64) * (LDH * 2) + b_off;

        #pragma unroll
        for (int s = 0; s < 4; ++s) {
            const uint32_t koff = (uint32_t)(s << 5);

            uint32_t ah[2][4];
            #pragma unroll
            for (int mf = 0; mf < 2; ++mf) {
                const uint32_t moff = (uint32_t)(mf * 16 * (LDH * 2)) + koff;
                ldm_x4(ah[mf][0], ah[mf][1], ah[mf][2], ah[mf][3], a_h + moff);
            }
            uint32_t bh[8][2];
            #pragma unroll
            for (int np = 0; np < 4; ++np) {
                const uint32_t noff = (uint32_t)(np * 16 * (LDH * 2)) + koff;
                uint32_t r0, r1, r2, r3;
                ldm_x4(r0, r1, r2, r3, b_h + noff);
                bh[np*2][0] = r0; bh[np*2][1] = r1; bh[np*2+1][0] = r2; bh[np*2+1][1] = r3;
            }
            #pragma unroll
            for (int mf = 0; mf < 2; ++mf)
                #pragma unroll
                for (int nf = 0; nf < 8; ++nf)
                    mma16(acc[mf][nf], ah[mf], bh[nf][0], bh[nf][1]);
        }

        // single barrier per iter: stage it+1 resident; buffer it%3 free
        asm volatile("cp.async.wait_group 1;");
        __syncthreads();
    }

    // ---- epilogue ----
    const bool hb = (bias != nullptr);
    const bool dostats = (rowsq != nullptr);
    #pragma unroll
    for (int mf = 0; mf < 2; ++mf) {
        const int r0 = bm + wm * 32 + mf * 16 + (lane >> 2);

        float sq_a = 0.f, sq_b = 0.f;
        float mx_a = -INFINITY, mx_b = -INFINITY;
        int   ix_a = 0, ix_b = 0;

        #pragma unroll
        for (int nf = 0; nf < 8; ++nf) {
            const int col = bn + wn * 64 + nf * 8 + ((lane & 3) << 1);
            float v[4];
            v[0] = acc[mf][nf][0]; v[1] = acc[mf][nf][1];
            v[2] = acc[mf][nf][2]; v[3] = acc[mf][nf][3];
            if (hb) {
                const float bx = bias[col], by = bias[col + 1];
                v[0] += bx; v[1] += by; v[2] += bx; v[3] += by;
            }
            if (relu) {
                v[0] = fmaxf(v[0], 0.f); v[1] = fmaxf(v[1], 0.f);
                v[2] = fmaxf(v[2], 0.f); v[3] = fmaxf(v[3], 0.f);
            }
            if (dostats) {
                sq_a += v[0] * v[0] + v[1] * v[1];
                sq_b += v[2] * v[2] + v[3] * v[3];
                if (v[0] > mx_a) { mx_a = v[0]; ix_a = col; }
                if (v[1] > mx_a) { mx_a = v[1]; ix_a = col + 1; }
                if (v[2] > mx_b) { mx_b = v[2]; ix_b = col; }
                if (v[3] > mx_b) { mx_b = v[3]; ix_b = col + 1; }
            }
            const size_t o0 = (size_t)r0 * N + col;
            const size_t o1 = (size_t)(r0 + 8) * N + col;
            hf h[4];
            h[0] = __float2half_rn(v[0]); h[1] = __float2half_rn(v[1]);
            h[2] = __float2half_rn(v[2]); h[3] = __float2half_rn(v[3]);
            *reinterpret_cast<uint32_t*>(Ch + o0) = *reinterpret_cast<uint32_t*>(h);
            *reinterpret_cast<uint32_t*>(Ch + o1) = *reinterpret_cast<uint32_t*>(h + 2);
        }

        if (dostats) {
            #pragma unroll
            for (int d = 1; d < 4; d <<= 1) {
                float osq = __shfl_xor_sync(0xFFFFFFFFu, sq_a, d);
                float omx = __shfl_xor_sync(0xFFFFFFFFu, mx_a, d);
                int   oix = __shfl_xor_sync(0xFFFFFFFFu, ix_a, d);
                sq_a += osq;
                if (omx > mx_a || (omx == mx_a && oix < ix_a)) { mx_a = omx; ix_a = oix; }
                osq = __shfl_xor_sync(0xFFFFFFFFu, sq_b, d);
                omx = __shfl_xor_sync(0xFFFFFFFFu, mx_b, d);
                oix = __shfl_xor_sync(0xFFFFFFFFu, ix_b, d);
                sq_b += osq;
                if (omx > mx_b || (omx == mx_b && oix < ix_b)) { mx_b = omx; ix_b = oix; }
            }
            if ((lane & 3) == 0) {
                atomicAdd(rowsq + r0,     sq_a);
                atomicAdd(rowsq + r0 + 8, sq_b);
                atomicMax(rowmax + r0,     pack_mi(mx_a, ix_a));
                atomicMax(rowmax + r0 + 8, pack_mi(mx_b, ix_b));
            }
        }
    }
}

// ---- single-pass row finish: exp-sum + picked + argmax check ---------------
__global__ __launch_bounds__(256)
void row_finish(const hf* __restrict__ sim, const int* __restrict__ target,
                const float* __restrict__ temp_p,
                const float* __restrict__ rowsq,
                const unsigned long long* __restrict__ rowmax,
                float* __restrict__ picked, int* __restrict__ correct) {
    const int row = blockIdx.x;
    const hf* s = sim + (size_t)row * NT;
    __shared__ float red[256];
    const int tid = threadIdx.x;

    const float sumsq = rowsq[row];
    const float c1 = sqrtf(sumsq);
    const float inv_c1 = 1.0f / c1;
    const float c2 = sqrtf(sumsq * inv_c1 * inv_c1);
    const float temp = temp_p[0];
    const float invt = 1.0f / (c2 * temp);
    const float scale = inv_c1 * invt;

    const unsigned long long packed = rowmax[row];
    const uint32_t mono = (uint32_t)(packed >> 32);
    const uint32_t ub = (mono & 0x80000000u) ? (mono & 0x7FFFFFFFu) : ~mono;
    const float gmax = __uint_as_float(ub);
    const int   amax = (int)(~(uint32_t)(packed & 0xFFFFFFFFull));
    const float lmax = gmax * scale;

    float se = 0.0f;
    const __half2* s2 = reinterpret_cast<const __half2*>(s);
    for (int j = tid; j < NT / 2; j += 256) {
        float2 p = __half22float2(s2[j]);
        se += expf(p.x * scale - lmax) + expf(p.y * scale - lmax);
    }
    red[tid] = se;
    __syncthreads();
    for (int st = 128; st > 0; st >>= 1) {
        if (tid < st) red[tid] += red[tid + st];
        __syncthreads();
    }
    if (tid == 0) {
        const float lse = lmax + logf(red[0]);
        const int t = target[row];
        picked[row]  = __half2float(s[t]) * scale - lse;
        correct[row] = (amax == t) ? 1 : 0;
    }
}

// ---------------- deterministic final reduce --------------------------------
__global__ __launch_bounds__(1024)
void finalize(const float* __restrict__ picked, const int* __restrict__ correct,
              float* __restrict__ out, int out_size) {
    __shared__ float sp[1024];
    __shared__ int   sc[1024];
    const int tid = threadIdx.x;
    float s = 0.0f; int c = 0;
    for (int i = tid; i < BB; i += 1024) { s += picked[i]; c += correct[i]; }
    sp[tid] = s; sc[tid] = c;
    __syncthreads();
    for (int st = 512; st > 0; st >>= 1) {
        if (tid < st) { sp[tid] += sp[tid + st]; sc[tid] += sc[tid + st]; }
        __syncthreads();
    }
    if (tid == 0) {
        out[0] = -sp[0] / (float)BB;
        if (out_size >= 2) out[1] = (float)sc[0];
    }
}

// ---------------- launch ----------------------------------------------------
#define SYM(v, s) cudaGetSymbolAddress((void**)&v, s)

extern "C" void kernel_launch(void* const* d_in, const int* in_sizes, int n_in,
                              void* d_out, int out_size) {
    const float* img  = (const float*)d_in[0];
    const float* txt  = (const float*)d_in[1];
    const int*   tgt  = (const int*)  d_in[2];
    const float* temp = (const float*)d_in[3];
    const float* Wi0 = (const float*)d_in[4];  const float* bi0 = (const float*)d_in[5];
    const float* Wi1 = (const float*)d_in[6];  const float* bi1 = (const float*)d_in[7];
    const float* Wi2 = (const float*)d_in[8];  const float* bi2 = (const float*)d_in[9];
    const float* Wt0 = (const float*)d_in[10]; const float* bt0 = (const float*)d_in[11];
    const float* Wt1 = (const float*)d_in[12]; const float* bt1 = (const float*)d_in[13];
    const float* Wt2 = (const float*)d_in[14]; const float* bt2 = (const float*)d_in[15];
    // d_in[16] = logit_scale : cancels under row L2-normalization, unused.
    float* out = (float*)d_out;

    hf *img_h, *txtT_h, *ht1_h, *ht2_h, *ptxt_h, *hi1_h, *hi2_h, *pimg_h;
    hf *Wi0T, *Wi1T, *Wi2T, *Wt0T, *Wt1T, *Wt2T, *sim;
    float *picked, *rowsq; unsigned long long *rowmax; int *corr;
    SYM(img_h,  g_img_h);
    SYM(txtT_h, g_txtT_h);
    SYM(ht1_h,  g_ht1_h);
    SYM(ht2_h,  g_ht2_h);
    SYM(ptxt_h, g_ptxt_h);
    SYM(hi1_h,  g_hi1_h);
    SYM(hi2_h,  g_hi2_h);
    SYM(pimg_h, g_pimg_h);
    SYM(Wi0T, g_Wi0T); SYM(Wi1T, g_Wi1T); SYM(Wi2T, g_Wi2T);
    SYM(Wt0T, g_Wt0T); SYM(Wt1T, g_Wt1T); SYM(Wt2T, g_Wt2T);
    SYM(sim, g_sim); SYM(picked, g_picked); SYM(corr, g_correct);
    SYM(rowsq, g_rowsq); SYM(rowmax, g_rowmax);

    cudaFuncSetAttribute(gemm_mma, cudaFuncAttributeMaxDynamicSharedMemorySize, GEMM_SMEM);

    static cudaStream_t s_txt = nullptr;
    static cudaEvent_t  ev_fork = nullptr, ev_join = nullptr;
    static bool fork_ok = false;
    if (!s_txt) {
        fork_ok = (cudaStreamCreateWithFlags(&s_txt, cudaStreamNonBlocking) == cudaSuccess)
               && (cudaEventCreateWithFlags(&ev_fork, cudaEventDisableTiming) == cudaSuccess)
               && (cudaEventCreateWithFlags(&ev_join, cudaEventDisableTiming) == cudaSuccess);
    }

    // ---- pre-kernels + stat-array clear ----
    cudaMemsetAsync(rowsq,  0, BB * sizeof(float), 0);
    cudaMemsetAsync(rowmax, 0, BB * sizeof(unsigned long long), 0);

    TP7 tp;
    tp.d[0] = { Wi0, Wi0T,  DD, HH };
    tp.d[1] = { Wi1, Wi1T,  HH, HH };
    tp.d[2] = { Wi2, Wi2T,  HH, DD };
    tp.d[3] = { Wt0, Wt0T,  DD, HH };
    tp.d[4] = { Wt1, Wt1T,  HH, HH };
    tp.d[5] = { Wt2, Wt2T,  HH, DD };
    tp.d[6] = { txt, txtT_h, DD, NT };
    transpose_multi_k<<<dim3(NT/32, HH/32, 7), dim3(32, 8)>>>(tp);
    cvt_k<<<256, 256>>>(img, img_h, (size_t)BB * DD / 4);

    // ---- fork: txt MLP on side stream, img MLP on main stream ----
    cudaStream_t st = 0;
    if (fork_ok) {
        cudaEventRecord(ev_fork, 0);
        cudaStreamWaitEvent(s_txt, ev_fork, 0);
        st = s_txt;
    }
    gemm_mma<<<dim3(HH/128, NT/128), 256, GEMM_SMEM, st>>>(
        txtT_h, Wt0T, bt0, ht1_h, nullptr, nullptr, NT, HH, DD, 1);
    gemm_mma<<<dim3(HH/128, NT/128), 256, GEMM_SMEM, st>>>(
        ht1_h, Wt1T, bt1, ht2_h, nullptr, nullptr, NT, HH, HH, 1);
    gemm_mma<<<dim3(DD/128, NT/128), 256, GEMM_SMEM, st>>>(
        ht2_h, Wt2T, bt2, ptxt_h, nullptr, nullptr, NT, DD, HH, 0);
    if (fork_ok) cudaEventRecord(ev_join, s_txt);

    gemm_mma<<<dim3(HH/128, BB/128), 256, GEMM_SMEM>>>(
        img_h, Wi0T, bi0, hi1_h, nullptr, nullptr, BB, HH, DD, 1);
    gemm_mma<<<dim3(HH/128, BB/128), 256, GEMM_SMEM>>>(
        hi1_h, Wi1T, bi1, hi2_h, nullptr, nullptr, BB, HH, HH, 1);
    gemm_mma<<<dim3(DD/128, BB/128), 256, GEMM_SMEM>>>(
        hi2_h, Wi2T, bi2, pimg_h, nullptr, nullptr, BB, DD, HH, 0);

    if (fork_ok) cudaStreamWaitEvent(0, ev_join, 0);   // join before sim

    // similarity: sim[BB, NT] = pimg @ ptxt^T  (fp16 out + fp32 stats)
    gemm_mma<<<dim3(NT/128, BB/128), 256, GEMM_SMEM>>>(
        pimg_h, ptxt_h, nullptr, sim, rowsq, rowmax, BB, NT, DD, 0);

    // single-pass per-row finish
    row_finish<<<BB, 256>>>(sim, tgt, temp, rowsq, rowmax, picked, corr);

    // final deterministic reduction
    finalize<<<1, 1024>>>(picked, corr, out, out_size);
}